// round 5
// baseline (speedup 1.0000x reference)
#include <cuda_runtime.h>
#include <math.h>

// Problem constants (fixed shapes for this problem instance)
#define B_    4
#define S_    1024
#define HID_  4096
#define NH_   32
#define NKV_  8
#define HD_   128
#define NNZ_  (B_ * S_)

// ---------------------------------------------------------------------------
// Scratch (static device allocations; runtime alloc is forbidden)
// ---------------------------------------------------------------------------
__device__ float g_q[(size_t)NNZ_ * NH_ * HD_];     // 64 MB  [tok, h, d]
__device__ float g_k[(size_t)NNZ_ * NKV_ * HD_];    // 16 MB  [tok, hk, d]
__device__ float g_v[(size_t)NNZ_ * NKV_ * HD_];    // 16 MB
__device__ float g_attn[(size_t)NNZ_ * NH_ * HD_];  // 64 MB  [tok, h, d]

// ---------------------------------------------------------------------------
// SGEMM: C[M,N] = A[M,K] * B[N,K]^T   (all fp32, row-major; K-contiguous both)
// 128x128 tile, BK=8, 256 threads, 8x8 per-thread microtile, register prefetch
// ---------------------------------------------------------------------------
__global__ __launch_bounds__(256, 2)
void sgemm_nt(const float* __restrict__ A, const float* __restrict__ Bm,
              float* __restrict__ C, int M, int N, int K) {
    __shared__ float As[8][128];
    __shared__ float Bs[8][128];

    const int m0 = blockIdx.y * 128;
    const int n0 = blockIdx.x * 128;
    const int tid = threadIdx.x;
    const int tm = tid >> 4;          // 0..15
    const int tn = tid & 15;          // 0..15
    const int lr = tid >> 1;          // 0..127 (load row)
    const int lc = (tid & 1) * 4;     // 0 or 4 (load col within BK)

    const float* Ab = A  + (size_t)(m0 + lr) * K + lc;
    const float* Bb = Bm + (size_t)(n0 + lr) * K + lc;

    float acc[8][8];
#pragma unroll
    for (int i = 0; i < 8; ++i)
#pragma unroll
        for (int j = 0; j < 8; ++j) acc[i][j] = 0.0f;

    float4 av = *(const float4*)Ab;
    float4 bv = *(const float4*)Bb;

    for (int k0 = 0; k0 < K; k0 += 8) {
        As[lc + 0][lr] = av.x; As[lc + 1][lr] = av.y;
        As[lc + 2][lr] = av.z; As[lc + 3][lr] = av.w;
        Bs[lc + 0][lr] = bv.x; Bs[lc + 1][lr] = bv.y;
        Bs[lc + 2][lr] = bv.z; Bs[lc + 3][lr] = bv.w;
        __syncthreads();

        if (k0 + 8 < K) {   // prefetch next tile into registers (hides GMEM latency)
            av = *(const float4*)(Ab + k0 + 8);
            bv = *(const float4*)(Bb + k0 + 8);
        }

#pragma unroll
        for (int k = 0; k < 8; ++k) {
            float ar[8], br[8];
            *(float4*)&ar[0] = *(const float4*)&As[k][tm * 8];
            *(float4*)&ar[4] = *(const float4*)&As[k][tm * 8 + 4];
            *(float4*)&br[0] = *(const float4*)&Bs[k][tn * 8];
            *(float4*)&br[4] = *(const float4*)&Bs[k][tn * 8 + 4];
#pragma unroll
            for (int i = 0; i < 8; ++i)
#pragma unroll
                for (int j = 0; j < 8; ++j)
                    acc[i][j] = fmaf(ar[i], br[j], acc[i][j]);
        }
        __syncthreads();
    }

#pragma unroll
    for (int i = 0; i < 8; ++i) {
        float* Cr = C + (size_t)(m0 + tm * 8 + i) * N + n0 + tn * 8;
        *(float4*)(Cr)     = make_float4(acc[i][0], acc[i][1], acc[i][2], acc[i][3]);
        *(float4*)(Cr + 4) = make_float4(acc[i][4], acc[i][5], acc[i][6], acc[i][7]);
    }
}

// ---------------------------------------------------------------------------
// Llama-3.1 RoPE applied in place to Q (32 heads) and K (8 heads).
// One block per token, 64 threads (one per rotation pair index d).
// ---------------------------------------------------------------------------
__global__ void rope_kernel(const int* __restrict__ pos_ids) {
    const int tok = blockIdx.x;
    const int d = threadIdx.x;                 // 0..63
    const float p = (float)pos_ids[tok];

    // freq = theta^(-d/64), matching jnp fp32 computation to ~1 ulp via double
    float fr = (float)pow(500000.0, -(double)d / 64.0);
    const float two_pi = 6.283185307179586f;
    float wav = two_pi / fr;
    float f;
    if (wav < 2048.0f) {                       // high_wl = 8192/4
        f = fr;
    } else if (wav > 8192.0f) {                // low_wl = 8192/1
        f = fr * 0.125f;
    } else {
        float smooth = (8192.0f / wav - 1.0f) * (1.0f / 3.0f);
        f = (1.0f - smooth) * fr * 0.125f + smooth * fr;
    }
    float ang = p * f;
    float c = cosf(ang);
    float s = sinf(ang);

    float* qb = g_q + (size_t)tok * (NH_ * HD_);
#pragma unroll 4
    for (int h = 0; h < NH_; ++h) {
        float x1 = qb[h * HD_ + d];
        float x2 = qb[h * HD_ + d + 64];
        qb[h * HD_ + d]      = x1 * c - x2 * s;
        qb[h * HD_ + d + 64] = x2 * c + x1 * s;
    }
    float* kb = g_k + (size_t)tok * (NKV_ * HD_);
#pragma unroll
    for (int h = 0; h < NKV_; ++h) {
        float x1 = kb[h * HD_ + d];
        float x2 = kb[h * HD_ + d + 64];
        kb[h * HD_ + d]      = x1 * c - x2 * s;
        kb[h * HD_ + d + 64] = x2 * c + x1 * s;
    }
}

// ---------------------------------------------------------------------------
// Flash attention (fp32, causal, GQA 4:1). Block = (qtile=64 rows, head, batch).
// 256 threads: 16x16 grid; scores 4x4/thread, O accum 4 rows x 8 cols/thread.
// smem: qs[128][64] (d-major), ks[128][64], vs[64][128], ps[64][65]
// ---------------------------------------------------------------------------
#define FA_SMEM_FLOATS (8192 + 8192 + 8192 + 64 * 65)
#define FA_SMEM_BYTES  (FA_SMEM_FLOATS * 4)

__global__ __launch_bounds__(256)
void fa_kernel() {
    extern __shared__ float smf[];
    float* qs = smf;               // [128][64]
    float* ks = smf + 8192;        // [128][64]
    float* vs = smf + 16384;       // [64][128]
    float* ps = smf + 24576;       // [64][65] padded stride (bank spread)

    const int qt = blockIdx.x;     // 0..15
    const int h  = blockIdx.y;     // 0..31
    const int b  = blockIdx.z;     // 0..3
    const int hk = h >> 2;         // GQA group
    const int tid = threadIdx.x;
    const int tm = tid >> 4;       // 0..15 (row group: rows tm*4..tm*4+3)
    const int tn = tid & 15;       // 0..15
    const int q0 = qt * 64;
    const size_t tok0 = (size_t)b * S_ + q0;
    const float scale = 0.08838834764831845f;   // 1/sqrt(128)

    // Load Q tile transposed into qs[d][row], pre-scaled
    {
        const float* gq = g_q + tok0 * (NH_ * HD_) + (size_t)h * HD_;
#pragma unroll
        for (int it = 0; it < 8; ++it) {
            int lin = it * 256 + tid;
            int row = lin >> 5;
            int c4  = (lin & 31) * 4;
            float4 v = *(const float4*)(gq + (size_t)row * (NH_ * HD_) + c4);
            qs[(c4 + 0) * 64 + row] = v.x * scale;
            qs[(c4 + 1) * 64 + row] = v.y * scale;
            qs[(c4 + 2) * 64 + row] = v.z * scale;
            qs[(c4 + 3) * 64 + row] = v.w * scale;
        }
    }

    float o[4][8];
#pragma unroll
    for (int i = 0; i < 4; ++i)
#pragma unroll
        for (int j = 0; j < 8; ++j) o[i][j] = 0.0f;
    float mrun[4] = {-1e30f, -1e30f, -1e30f, -1e30f};
    float lrun[4] = {0.0f, 0.0f, 0.0f, 0.0f};

    for (int jt = 0; jt <= qt; ++jt) {
        // Load K (transposed) and V (row-major) tiles
        const float* gk = g_k + ((size_t)b * S_ + jt * 64) * (NKV_ * HD_) + (size_t)hk * HD_;
        const float* gv = g_v + ((size_t)b * S_ + jt * 64) * (NKV_ * HD_) + (size_t)hk * HD_;
#pragma unroll
        for (int it = 0; it < 8; ++it) {
            int lin = it * 256 + tid;
            int row = lin >> 5;
            int c4  = (lin & 31) * 4;
            float4 kv = *(const float4*)(gk + (size_t)row * (NKV_ * HD_) + c4);
            ks[(c4 + 0) * 64 + row] = kv.x;
            ks[(c4 + 1) * 64 + row] = kv.y;
            ks[(c4 + 2) * 64 + row] = kv.z;
            ks[(c4 + 3) * 64 + row] = kv.w;
            float4 vv = *(const float4*)(gv + (size_t)row * (NKV_ * HD_) + c4);
            *(float4*)&vs[row * 128 + c4] = vv;
        }
        __syncthreads();

        // Scores S = Qs^T * Ks  (each thread 4x4)
        float s[4][4];
#pragma unroll
        for (int i = 0; i < 4; ++i)
#pragma unroll
            for (int j = 0; j < 4; ++j) s[i][j] = 0.0f;

#pragma unroll 4
        for (int d = 0; d < 128; ++d) {
            float4 aq = *(const float4*)&qs[d * 64 + tm * 4];
            float4 kq = *(const float4*)&ks[d * 64 + tn * 4];
            float aa[4] = {aq.x, aq.y, aq.z, aq.w};
            float bb[4] = {kq.x, kq.y, kq.z, kq.w};
#pragma unroll
            for (int i = 0; i < 4; ++i)
#pragma unroll
                for (int j = 0; j < 4; ++j)
                    s[i][j] = fmaf(aa[i], bb[j], s[i][j]);
        }

        // Causal mask (only the diagonal tile needs it)
        if (jt == qt) {
#pragma unroll
            for (int i = 0; i < 4; ++i) {
                int ql = tm * 4 + i;
#pragma unroll
                for (int j = 0; j < 4; ++j) {
                    int kl = tn * 4 + j;
                    if (kl > ql) s[i][j] = -1e30f;
                }
            }
        }

        // Online softmax (row stats shared across the 16-lane row group)
        float corr[4];
#pragma unroll
        for (int i = 0; i < 4; ++i) {
            float t = fmaxf(fmaxf(s[i][0], s[i][1]), fmaxf(s[i][2], s[i][3]));
            t = fmaxf(t, __shfl_xor_sync(0xffffffffu, t, 8));
            t = fmaxf(t, __shfl_xor_sync(0xffffffffu, t, 4));
            t = fmaxf(t, __shfl_xor_sync(0xffffffffu, t, 2));
            t = fmaxf(t, __shfl_xor_sync(0xffffffffu, t, 1));
            float mnew = fmaxf(mrun[i], t);
            corr[i] = __expf(mrun[i] - mnew);
            mrun[i] = mnew;
        }
#pragma unroll
        for (int i = 0; i < 4; ++i) {
            float rs = 0.0f;
#pragma unroll
            for (int j = 0; j < 4; ++j) {
                float pp = __expf(s[i][j] - mrun[i]);
                ps[(tn * 4 + j) * 65 + tm * 4 + i] = pp;   // transposed (k-major)
                rs += pp;
            }
            rs += __shfl_xor_sync(0xffffffffu, rs, 8);
            rs += __shfl_xor_sync(0xffffffffu, rs, 4);
            rs += __shfl_xor_sync(0xffffffffu, rs, 2);
            rs += __shfl_xor_sync(0xffffffffu, rs, 1);
            lrun[i] = lrun[i] * corr[i] + rs;
#pragma unroll
            for (int j = 0; j < 8; ++j) o[i][j] *= corr[i];
        }
        __syncthreads();   // ps visible to all before PV

        // O += P * V  (each thread 4 rows x 8 cols)
#pragma unroll 2
        for (int c = 0; c < 64; ++c) {
            float p0 = ps[c * 65 + tm * 4 + 0];
            float p1 = ps[c * 65 + tm * 4 + 1];
            float p2 = ps[c * 65 + tm * 4 + 2];
            float p3 = ps[c * 65 + tm * 4 + 3];
            float4 v0 = *(const float4*)&vs[c * 128 + tn * 8];
            float4 v1 = *(const float4*)&vs[c * 128 + tn * 8 + 4];
            float vv[8] = {v0.x, v0.y, v0.z, v0.w, v1.x, v1.y, v1.z, v1.w};
#pragma unroll
            for (int j = 0; j < 8; ++j) {
                o[0][j] = fmaf(p0, vv[j], o[0][j]);
                o[1][j] = fmaf(p1, vv[j], o[1][j]);
                o[2][j] = fmaf(p2, vv[j], o[2][j]);
                o[3][j] = fmaf(p3, vv[j], o[3][j]);
            }
        }
        __syncthreads();   // done reading ks/vs/ps before next tile's loads
    }

    // Epilogue: normalize, store to g_attn [tok, h*128 + col]
#pragma unroll
    for (int i = 0; i < 4; ++i) {
        float inv = 1.0f / lrun[i];
        float* dst = g_attn + (tok0 + tm * 4 + i) * (size_t)(NH_ * HD_)
                     + (size_t)h * HD_ + tn * 8;
        *(float4*)(dst)     = make_float4(o[i][0] * inv, o[i][1] * inv,
                                          o[i][2] * inv, o[i][3] * inv);
        *(float4*)(dst + 4) = make_float4(o[i][4] * inv, o[i][5] * inv,
                                          o[i][6] * inv, o[i][7] * inv);
    }
}

// ---------------------------------------------------------------------------
// Launch: QKV projections -> RoPE -> flash attention -> O projection.
// kv_cache append is skipped: cache starts zero, every slot is written exactly
// once, and the gather reconstructs exactly K/V — and the cache is not output.
// ---------------------------------------------------------------------------
extern "C" void kernel_launch(void* const* d_in, const int* in_sizes, int n_in,
                              void* d_out, int out_size) {
    const float* hs = (const float*)d_in[0];   // hidden_states [NNZ, HID]
    const float* wq = (const float*)d_in[1];   // [NH*HD, HID]
    const float* wk = (const float*)d_in[2];   // [NKV*HD, HID]
    const float* wv = (const float*)d_in[3];   // [NKV*HD, HID]
    const float* wo = (const float*)d_in[4];   // [HID, NH*HD]
    const int* pos  = (const int*)d_in[6];     // position_ids [NNZ]
    float* out = (float*)d_out;                // [NNZ, HID]

    float *pq, *pk, *pv, *pa;
    cudaGetSymbolAddress((void**)&pq, g_q);
    cudaGetSymbolAddress((void**)&pk, g_k);
    cudaGetSymbolAddress((void**)&pv, g_v);
    cudaGetSymbolAddress((void**)&pa, g_attn);

    cudaFuncSetAttribute(fa_kernel, cudaFuncAttributeMaxDynamicSharedMemorySize,
                         FA_SMEM_BYTES);

    // QKV projections
    sgemm_nt<<<dim3(NH_ * HD_ / 128, NNZ_ / 128), 256>>>(hs, wq, pq, NNZ_, NH_ * HD_, HID_);
    sgemm_nt<<<dim3(NKV_ * HD_ / 128, NNZ_ / 128), 256>>>(hs, wk, pk, NNZ_, NKV_ * HD_, HID_);
    sgemm_nt<<<dim3(NKV_ * HD_ / 128, NNZ_ / 128), 256>>>(hs, wv, pv, NNZ_, NKV_ * HD_, HID_);

    // RoPE on Q and K (in place)
    rope_kernel<<<NNZ_, 64>>>(pos);

    // Causal GQA attention
    fa_kernel<<<dim3(S_ / 64, NH_, B_), 256, FA_SMEM_BYTES>>>();

    // Output projection
    sgemm_nt<<<dim3(HID_ / 128, NNZ_ / 128), 256>>>(pa, wo, out, NNZ_, HID_, HID_);
}

// round 8
// speedup vs baseline: 1.8757x; 1.8757x over previous
#include <cuda_runtime.h>
#include <cuda_bf16.h>
#include <math.h>
#include <stdint.h>

// Problem constants
#define B_    4
#define S_    1024
#define HID_  4096
#define NH_   32
#define NKV_  8
#define HD_   128
#define NNZ_  (B_ * S_)

// ---------------------------------------------------------------------------
// Scratch (static device allocations; runtime alloc is forbidden)
// ---------------------------------------------------------------------------
__device__ float g_q[(size_t)NNZ_ * NH_ * HD_];     // [tok, h, d] fp32
__device__ float g_k[(size_t)NNZ_ * NKV_ * HD_];
__device__ float g_v[(size_t)NNZ_ * NKV_ * HD_];
__device__ float g_attn[(size_t)NNZ_ * NH_ * HD_];

// bf16 split planes (hi/lo)
__device__ __nv_bfloat16 g_hs_h[(size_t)NNZ_ * HID_];
__device__ __nv_bfloat16 g_hs_l[(size_t)NNZ_ * HID_];
__device__ __nv_bfloat16 g_wq_h[(size_t)(NH_ * HD_) * HID_];
__device__ __nv_bfloat16 g_wq_l[(size_t)(NH_ * HD_) * HID_];
__device__ __nv_bfloat16 g_wk_h[(size_t)(NKV_ * HD_) * HID_];
__device__ __nv_bfloat16 g_wk_l[(size_t)(NKV_ * HD_) * HID_];
__device__ __nv_bfloat16 g_wv_h[(size_t)(NKV_ * HD_) * HID_];
__device__ __nv_bfloat16 g_wv_l[(size_t)(NKV_ * HD_) * HID_];
__device__ __nv_bfloat16 g_wo_h[(size_t)HID_ * (NH_ * HD_)];
__device__ __nv_bfloat16 g_wo_l[(size_t)HID_ * (NH_ * HD_)];
__device__ __nv_bfloat16 g_at_h[(size_t)NNZ_ * (NH_ * HD_)];
__device__ __nv_bfloat16 g_at_l[(size_t)NNZ_ * (NH_ * HD_)];

// ---------------------------------------------------------------------------
// PTX helpers — sm_80-compatible vocabulary ONLY (harness PTX targets
// compute_103 without the 'a' suffix, so tcgen05/TMA are unavailable).
// ---------------------------------------------------------------------------
__device__ __forceinline__ uint32_t s2u(const void* p) {
    uint32_t a;
    asm("{ .reg .u64 t; cvta.to.shared.u64 t, %1; cvt.u32.u64 %0, t; }"
        : "=r"(a) : "l"(p));
    return a;
}

__device__ __forceinline__ void cp16(uint32_t s, const void* g) {
    asm volatile("cp.async.cg.shared.global [%0], [%1], 16;" :: "r"(s), "l"(g));
}
#define CP_COMMIT() asm volatile("cp.async.commit_group;" ::: "memory")
#define CP_WAIT(n)  asm volatile("cp.async.wait_group %0;" :: "n"(n) : "memory")

__device__ __forceinline__ void ldm_x4(uint32_t* r, uint32_t addr) {
    asm volatile("ldmatrix.sync.aligned.m8n8.x4.shared.b16 {%0,%1,%2,%3}, [%4];"
                 : "=r"(r[0]), "=r"(r[1]), "=r"(r[2]), "=r"(r[3]) : "r"(addr));
}

__device__ __forceinline__ void mma16816(float* d, const uint32_t* a,
                                         const uint32_t* b) {
    asm volatile(
        "mma.sync.aligned.m16n8k16.row.col.f32.bf16.bf16.f32 "
        "{%0,%1,%2,%3}, {%4,%5,%6,%7}, {%8,%9}, {%0,%1,%2,%3};"
        : "+f"(d[0]), "+f"(d[1]), "+f"(d[2]), "+f"(d[3])
        : "r"(a[0]), "r"(a[1]), "r"(a[2]), "r"(a[3]), "r"(b[0]), "r"(b[1]));
}

// ---------------------------------------------------------------------------
// Split fp32 -> (bf16 hi, bf16 lo) planes.
// ---------------------------------------------------------------------------
__global__ void split_fp32_bf16(const float* __restrict__ src,
                                __nv_bfloat16* __restrict__ hi,
                                __nv_bfloat16* __restrict__ lo) {
    size_t i = (size_t)blockIdx.x * blockDim.x + threadIdx.x;
    float4 v = ((const float4*)src)[i];
    float x[4] = {v.x, v.y, v.z, v.w};
    union { __nv_bfloat16 b[4]; ushort4 u; } H, L;
#pragma unroll
    for (int j = 0; j < 4; ++j) {
        H.b[j] = __float2bfloat16(x[j]);
        L.b[j] = __float2bfloat16(x[j] - __bfloat162float(H.b[j]));
    }
    ((ushort4*)hi)[i] = H.u;
    ((ushort4*)lo)[i] = L.u;
}

// ---------------------------------------------------------------------------
// bf16-split GEMM via mma.sync (legacy HMMA — works on plain compute_103):
// C[M,N] = (Ah+Al)[M,K] * (Bh+Bl)[N,K]^T, dropping the Al*Bl term.
// 128x128 block tile, BK=32, 3-stage cp.async, 8 warps as 4(M)x2(N),
// warp tile 32x64 via m16n8k16 (2 M-frags x 8 N-frags x 3 products).
// smem/stage: Ah|Al|Bh|Bl, each [128][32] bf16 (8KB) -> 32KB; 3 stages = 96KB.
// Swizzle: 16B chunk (row, cg) at row*64 + ((cg ^ ((row>>1)&3))<<4).
// ---------------------------------------------------------------------------
#define PLANE_B   8192
#define STAGE_B   (4 * PLANE_B)
#define G_SMEM    (3 * STAGE_B)

__global__ __launch_bounds__(256, 1)
void gemm_mma_split(const __nv_bfloat16* __restrict__ Ah,
                    const __nv_bfloat16* __restrict__ Al,
                    const __nv_bfloat16* __restrict__ Bh,
                    const __nv_bfloat16* __restrict__ Bl,
                    float* __restrict__ C, int N, int K) {
    extern __shared__ char smc[];
    const uint32_t sb = s2u(smc);
    const int tid  = threadIdx.x;
    const int wid  = tid >> 5, lane = tid & 31;
    const int wm   = wid >> 1, wn = wid & 1;       // warp grid 4x2
    const int m0   = blockIdx.y * 128, n0 = blockIdx.x * 128;

    // ---- cp.async geometry: thread -> (row 0..127, two 16B chunks) ----
    const int lrow = tid >> 1;
    const int cg0  = (tid & 1) * 2;                // chunks cg0, cg0+1 (of 4)
    const __nv_bfloat16* gAh = Ah + (size_t)(m0 + lrow) * K + cg0 * 8;
    const __nv_bfloat16* gAl = Al + (size_t)(m0 + lrow) * K + cg0 * 8;
    const __nv_bfloat16* gBh = Bh + (size_t)(n0 + lrow) * K + cg0 * 8;
    const __nv_bfloat16* gBl = Bl + (size_t)(n0 + lrow) * K + cg0 * 8;
    const int swl = (lrow >> 1) & 3;
    uint32_t soff[2];
    soff[0] = lrow * 64 + (((cg0 + 0) ^ swl) << 4);
    soff[1] = lrow * 64 + (((cg0 + 1) ^ swl) << 4);

#define LOAD_CHUNK(kt, st) do {                                          \
        uint32_t b_ = sb + (st) * STAGE_B;                               \
        size_t  g_ = (size_t)(kt) * 32;                                  \
        cp16(b_ + soff[0],               gAh + g_);                      \
        cp16(b_ + soff[1],               gAh + g_ + 8);                  \
        cp16(b_ + PLANE_B + soff[0],     gAl + g_);                      \
        cp16(b_ + PLANE_B + soff[1],     gAl + g_ + 8);                  \
        cp16(b_ + 2 * PLANE_B + soff[0], gBh + g_);                      \
        cp16(b_ + 2 * PLANE_B + soff[1], gBh + g_ + 8);                  \
        cp16(b_ + 3 * PLANE_B + soff[0], gBl + g_);                      \
        cp16(b_ + 3 * PLANE_B + soff[1], gBl + g_ + 8);                  \
        CP_COMMIT();                                                     \
    } while (0)

    // ---- ldmatrix address offsets (per lane, within a plane) ----
    // A fragments: t in {0,1}; kk-half h in {0,1}
    uint32_t aoff[2][2];
#pragma unroll
    for (int t = 0; t < 2; ++t) {
        int row = wm * 32 + t * 16 + (lane & 15);
        int sw  = (row >> 1) & 3;
#pragma unroll
        for (int h = 0; h < 2; ++h) {
            int cg = 2 * h + (lane >> 4);
            aoff[t][h] = row * 64 + ((cg ^ sw) << 4);
        }
    }
    // B fragments: pair j in {0..3} (covers n-tiles 2j, 2j+1)
    uint32_t boff[4][2];
#pragma unroll
    for (int j = 0; j < 4; ++j) {
        int row = wn * 64 + j * 16 + ((lane >> 4) << 3) + (lane & 7);
        int sw  = (row >> 1) & 3;
#pragma unroll
        for (int h = 0; h < 2; ++h) {
            int cg = 2 * h + ((lane >> 3) & 1);
            boff[j][h] = row * 64 + ((cg ^ sw) << 4);
        }
    }

    float acc[2][8][4];
#pragma unroll
    for (int t = 0; t < 2; ++t)
#pragma unroll
        for (int n = 0; n < 8; ++n)
#pragma unroll
            for (int e = 0; e < 4; ++e) acc[t][n][e] = 0.0f;

    const int nkt = K >> 5;            // K-chunks of 32
    LOAD_CHUNK(0, 0);
    LOAD_CHUNK(1, 1);

    for (int kt = 0; kt < nkt; ++kt) {
        const int s = kt % 3;
        if (kt + 1 < nkt) { CP_WAIT(1); } else { CP_WAIT(0); }
        __syncthreads();               // stage s resident; prev compute done
        if (kt + 2 < nkt) LOAD_CHUNK(kt + 2, (kt + 2) % 3);

        const uint32_t pA_h = sb + s * STAGE_B;
        const uint32_t pA_l = pA_h + PLANE_B;
        const uint32_t pB_h = pA_h + 2 * PLANE_B;
        const uint32_t pB_l = pA_h + 3 * PLANE_B;

#pragma unroll
        for (int h = 0; h < 2; ++h) {  // two k16 steps per BK=32
            uint32_t ah[2][4], al[2][4], bh[4][4], bl[4][4];
#pragma unroll
            for (int t = 0; t < 2; ++t) {
                ldm_x4(ah[t], pA_h + aoff[t][h]);
                ldm_x4(al[t], pA_l + aoff[t][h]);
            }
#pragma unroll
            for (int j = 0; j < 4; ++j) {
                ldm_x4(bh[j], pB_h + boff[j][h]);
                ldm_x4(bl[j], pB_l + boff[j][h]);
            }
#pragma unroll
            for (int t = 0; t < 2; ++t)
#pragma unroll
                for (int j = 0; j < 4; ++j) {
                    mma16816(acc[t][2 * j],     ah[t], &bh[j][0]);
                    mma16816(acc[t][2 * j + 1], ah[t], &bh[j][2]);
                    mma16816(acc[t][2 * j],     ah[t], &bl[j][0]);
                    mma16816(acc[t][2 * j + 1], ah[t], &bl[j][2]);
                    mma16816(acc[t][2 * j],     al[t], &bh[j][0]);
                    mma16816(acc[t][2 * j + 1], al[t], &bh[j][2]);
                }
        }
    }

    // ---- epilogue: d-frag lane mapping (row = l>>2 (+8), col = 2*(l&3)) ----
    float* Cw = C + (size_t)(m0 + wm * 32) * N + n0 + wn * 64;
#pragma unroll
    for (int t = 0; t < 2; ++t)
#pragma unroll
        for (int n = 0; n < 8; ++n) {
            int r = t * 16 + (lane >> 2);
            int c = n * 8 + (lane & 3) * 2;
            *(float2*)&Cw[(size_t)r * N + c] =
                make_float2(acc[t][n][0], acc[t][n][1]);
            *(float2*)&Cw[(size_t)(r + 8) * N + c] =
                make_float2(acc[t][n][2], acc[t][n][3]);
        }
#undef LOAD_CHUNK
}

// ---------------------------------------------------------------------------
// Llama-3.1 RoPE in place on Q (32 heads) and K (8 heads). Block=token.
// ---------------------------------------------------------------------------
__global__ void rope_kernel(const int* __restrict__ pos_ids) {
    const int tok = blockIdx.x;
    const int d = threadIdx.x;                 // 0..63
    const float p = (float)pos_ids[tok];

    float fr = (float)pow(500000.0, -(double)d / 64.0);
    const float two_pi = 6.283185307179586f;
    float wav = two_pi / fr;
    float f;
    if (wav < 2048.0f)       f = fr;
    else if (wav > 8192.0f)  f = fr * 0.125f;
    else {
        float smooth = (8192.0f / wav - 1.0f) * (1.0f / 3.0f);
        f = (1.0f - smooth) * fr * 0.125f + smooth * fr;
    }
    float ang = p * f;
    float c = cosf(ang), s = sinf(ang);

    float* qb = g_q + (size_t)tok * (NH_ * HD_);
#pragma unroll 4
    for (int h = 0; h < NH_; ++h) {
        float x1 = qb[h * HD_ + d];
        float x2 = qb[h * HD_ + d + 64];
        qb[h * HD_ + d]      = x1 * c - x2 * s;
        qb[h * HD_ + d + 64] = x2 * c + x1 * s;
    }
    float* kb = g_k + (size_t)tok * (NKV_ * HD_);
#pragma unroll
    for (int h = 0; h < NKV_; ++h) {
        float x1 = kb[h * HD_ + d];
        float x2 = kb[h * HD_ + d + 64];
        kb[h * HD_ + d]      = x1 * c - x2 * s;
        kb[h * HD_ + d + 64] = x2 * c + x1 * s;
    }
}

// ---------------------------------------------------------------------------
// Flash attention (fp32, causal, GQA 4:1) — unchanged (passing since R3).
// ---------------------------------------------------------------------------
#define FA_SMEM_FLOATS (8192 + 8192 + 8192 + 64 * 65)
#define FA_SMEM_BYTES  (FA_SMEM_FLOATS * 4)

__global__ __launch_bounds__(256)
void fa_kernel() {
    extern __shared__ float smf[];
    float* qs = smf;               // [128][64]
    float* ks = smf + 8192;        // [128][64]
    float* vs = smf + 16384;       // [64][128]
    float* ps = smf + 24576;       // [64][65]

    const int qt = blockIdx.x;
    const int h  = blockIdx.y;
    const int b  = blockIdx.z;
    const int hk = h >> 2;
    const int tid = threadIdx.x;
    const int tm = tid >> 4;
    const int tn = tid & 15;
    const int q0 = qt * 64;
    const size_t tok0 = (size_t)b * S_ + q0;
    const float scale = 0.08838834764831845f;

    {
        const float* gq = g_q + tok0 * (NH_ * HD_) + (size_t)h * HD_;
#pragma unroll
        for (int it = 0; it < 8; ++it) {
            int lin = it * 256 + tid;
            int row = lin >> 5;
            int c4  = (lin & 31) * 4;
            float4 v = *(const float4*)(gq + (size_t)row * (NH_ * HD_) + c4);
            qs[(c4 + 0) * 64 + row] = v.x * scale;
            qs[(c4 + 1) * 64 + row] = v.y * scale;
            qs[(c4 + 2) * 64 + row] = v.z * scale;
            qs[(c4 + 3) * 64 + row] = v.w * scale;
        }
    }

    float o[4][8];
#pragma unroll
    for (int i = 0; i < 4; ++i)
#pragma unroll
        for (int j = 0; j < 8; ++j) o[i][j] = 0.0f;
    float mrun[4] = {-1e30f, -1e30f, -1e30f, -1e30f};
    float lrun[4] = {0.0f, 0.0f, 0.0f, 0.0f};

    for (int jt = 0; jt <= qt; ++jt) {
        const float* gk = g_k + ((size_t)b * S_ + jt * 64) * (NKV_ * HD_) + (size_t)hk * HD_;
        const float* gv = g_v + ((size_t)b * S_ + jt * 64) * (NKV_ * HD_) + (size_t)hk * HD_;
#pragma unroll
        for (int it = 0; it < 8; ++it) {
            int lin = it * 256 + tid;
            int row = lin >> 5;
            int c4  = (lin & 31) * 4;
            float4 kv = *(const float4*)(gk + (size_t)row * (NKV_ * HD_) + c4);
            ks[(c4 + 0) * 64 + row] = kv.x;
            ks[(c4 + 1) * 64 + row] = kv.y;
            ks[(c4 + 2) * 64 + row] = kv.z;
            ks[(c4 + 3) * 64 + row] = kv.w;
            float4 vv = *(const float4*)(gv + (size_t)row * (NKV_ * HD_) + c4);
            *(float4*)&vs[row * 128 + c4] = vv;
        }
        __syncthreads();

        float s[4][4];
#pragma unroll
        for (int i = 0; i < 4; ++i)
#pragma unroll
            for (int j = 0; j < 4; ++j) s[i][j] = 0.0f;

#pragma unroll 4
        for (int d = 0; d < 128; ++d) {
            float4 aq = *(const float4*)&qs[d * 64 + tm * 4];
            float4 kq = *(const float4*)&ks[d * 64 + tn * 4];
            float aa[4] = {aq.x, aq.y, aq.z, aq.w};
            float bb[4] = {kq.x, kq.y, kq.z, kq.w};
#pragma unroll
            for (int i = 0; i < 4; ++i)
#pragma unroll
                for (int j = 0; j < 4; ++j)
                    s[i][j] = fmaf(aa[i], bb[j], s[i][j]);
        }

        if (jt == qt) {
#pragma unroll
            for (int i = 0; i < 4; ++i) {
                int ql = tm * 4 + i;
#pragma unroll
                for (int j = 0; j < 4; ++j) {
                    int kl = tn * 4 + j;
                    if (kl > ql) s[i][j] = -1e30f;
                }
            }
        }

        float corr[4];
#pragma unroll
        for (int i = 0; i < 4; ++i) {
            float t = fmaxf(fmaxf(s[i][0], s[i][1]), fmaxf(s[i][2], s[i][3]));
            t = fmaxf(t, __shfl_xor_sync(0xffffffffu, t, 8));
            t = fmaxf(t, __shfl_xor_sync(0xffffffffu, t, 4));
            t = fmaxf(t, __shfl_xor_sync(0xffffffffu, t, 2));
            t = fmaxf(t, __shfl_xor_sync(0xffffffffu, t, 1));
            float mnew = fmaxf(mrun[i], t);
            corr[i] = __expf(mrun[i] - mnew);
            mrun[i] = mnew;
        }
#pragma unroll
        for (int i = 0; i < 4; ++i) {
            float rs = 0.0f;
#pragma unroll
            for (int j = 0; j < 4; ++j) {
                float pp = __expf(s[i][j] - mrun[i]);
                ps[(tn * 4 + j) * 65 + tm * 4 + i] = pp;
                rs += pp;
            }
            rs += __shfl_xor_sync(0xffffffffu, rs, 8);
            rs += __shfl_xor_sync(0xffffffffu, rs, 4);
            rs += __shfl_xor_sync(0xffffffffu, rs, 2);
            rs += __shfl_xor_sync(0xffffffffu, rs, 1);
            lrun[i] = lrun[i] * corr[i] + rs;
#pragma unroll
            for (int j = 0; j < 8; ++j) o[i][j] *= corr[i];
        }
        __syncthreads();

#pragma unroll 2
        for (int c = 0; c < 64; ++c) {
            float p0 = ps[c * 65 + tm * 4 + 0];
            float p1 = ps[c * 65 + tm * 4 + 1];
            float p2 = ps[c * 65 + tm * 4 + 2];
            float p3 = ps[c * 65 + tm * 4 + 3];
            float4 v0 = *(const float4*)&vs[c * 128 + tn * 8];
            float4 v1 = *(const float4*)&vs[c * 128 + tn * 8 + 4];
            float vv[8] = {v0.x, v0.y, v0.z, v0.w, v1.x, v1.y, v1.z, v1.w};
#pragma unroll
            for (int j = 0; j < 8; ++j) {
                o[0][j] = fmaf(p0, vv[j], o[0][j]);
                o[1][j] = fmaf(p1, vv[j], o[1][j]);
                o[2][j] = fmaf(p2, vv[j], o[2][j]);
                o[3][j] = fmaf(p3, vv[j], o[3][j]);
            }
        }
        __syncthreads();
    }

#pragma unroll
    for (int i = 0; i < 4; ++i) {
        float inv = 1.0f / lrun[i];
        float* dst = g_attn + (tok0 + tm * 4 + i) * (size_t)(NH_ * HD_)
                     + (size_t)h * HD_ + tn * 8;
        *(float4*)(dst)     = make_float4(o[i][0] * inv, o[i][1] * inv,
                                          o[i][2] * inv, o[i][3] * inv);
        *(float4*)(dst + 4) = make_float4(o[i][4] * inv, o[i][5] * inv,
                                          o[i][6] * inv, o[i][7] * inv);
    }
}

// ---------------------------------------------------------------------------
// Launch: split -> mma GEMMs (QKV) -> RoPE -> FA -> split -> mma GEMM (O).
// kv_cache append is skipped (identity round-trip; cache not an output).
// ---------------------------------------------------------------------------
extern "C" void kernel_launch(void* const* d_in, const int* in_sizes, int n_in,
                              void* d_out, int out_size) {
    const float* hs = (const float*)d_in[0];
    const float* wq = (const float*)d_in[1];
    const float* wk = (const float*)d_in[2];
    const float* wv = (const float*)d_in[3];
    const float* wo = (const float*)d_in[4];
    const int* pos  = (const int*)d_in[6];
    float* out = (float*)d_out;

    float *pq, *pk, *pv, *pa;
    cudaGetSymbolAddress((void**)&pq, g_q);
    cudaGetSymbolAddress((void**)&pk, g_k);
    cudaGetSymbolAddress((void**)&pv, g_v);
    cudaGetSymbolAddress((void**)&pa, g_attn);

    __nv_bfloat16 *hsh, *hsl, *wqh, *wql, *wkh, *wkl, *wvh, *wvl, *woh, *wol, *ath, *atl;
    cudaGetSymbolAddress((void**)&hsh, g_hs_h); cudaGetSymbolAddress((void**)&hsl, g_hs_l);
    cudaGetSymbolAddress((void**)&wqh, g_wq_h); cudaGetSymbolAddress((void**)&wql, g_wq_l);
    cudaGetSymbolAddress((void**)&wkh, g_wk_h); cudaGetSymbolAddress((void**)&wkl, g_wk_l);
    cudaGetSymbolAddress((void**)&wvh, g_wv_h); cudaGetSymbolAddress((void**)&wvl, g_wv_l);
    cudaGetSymbolAddress((void**)&woh, g_wo_h); cudaGetSymbolAddress((void**)&wol, g_wo_l);
    cudaGetSymbolAddress((void**)&ath, g_at_h); cudaGetSymbolAddress((void**)&atl, g_at_l);

    cudaFuncSetAttribute(fa_kernel, cudaFuncAttributeMaxDynamicSharedMemorySize,
                         FA_SMEM_BYTES);
    cudaFuncSetAttribute(gemm_mma_split, cudaFuncAttributeMaxDynamicSharedMemorySize,
                         G_SMEM);

    const int BIG4 = (NNZ_ * HID_) / 1024;          // 256 thr x 4 elems/thread
    const int SML4 = (NKV_ * HD_ * HID_) / 1024;

    // split inputs/weights to bf16 hi/lo planes
    split_fp32_bf16<<<BIG4, 256>>>(hs, hsh, hsl);
    split_fp32_bf16<<<BIG4, 256>>>(wq, wqh, wql);
    split_fp32_bf16<<<SML4, 256>>>(wk, wkh, wkl);
    split_fp32_bf16<<<SML4, 256>>>(wv, wvh, wvl);
    split_fp32_bf16<<<BIG4, 256>>>(wo, woh, wol);

    // QKV projections (tensor cores via mma.sync)
    gemm_mma_split<<<dim3((NH_ * HD_) / 128, NNZ_ / 128), 256, G_SMEM>>>(
        hsh, hsl, wqh, wql, pq, NH_ * HD_, HID_);
    gemm_mma_split<<<dim3((NKV_ * HD_) / 128, NNZ_ / 128), 256, G_SMEM>>>(
        hsh, hsl, wkh, wkl, pk, NKV_ * HD_, HID_);
    gemm_mma_split<<<dim3((NKV_ * HD_) / 128, NNZ_ / 128), 256, G_SMEM>>>(
        hsh, hsl, wvh, wvl, pv, NKV_ * HD_, HID_);

    // RoPE (in place, fp32)
    rope_kernel<<<NNZ_, 64>>>(pos);

    // Causal GQA attention (fp32)
    fa_kernel<<<dim3(S_ / 64, NH_, B_), 256, FA_SMEM_BYTES>>>();

    // split attention output, then O projection
    split_fp32_bf16<<<BIG4, 256>>>(pa, ath, atl);
    gemm_mma_split<<<dim3(HID_ / 128, NNZ_ / 128), 256, G_SMEM>>>(
        ath, atl, woh, wol, out, HID_, NH_ * HD_);
}

// round 9
// speedup vs baseline: 1.8993x; 1.0126x over previous
#include <cuda_runtime.h>
#include <cuda_bf16.h>
#include <math.h>
#include <stdint.h>

// Problem constants
#define B_    4
#define S_    1024
#define HID_  4096
#define NH_   32
#define NKV_  8
#define HD_   128
#define NNZ_  (B_ * S_)

// ---------------------------------------------------------------------------
// Scratch (static device allocations; runtime alloc is forbidden)
// ---------------------------------------------------------------------------
__device__ float g_q[(size_t)NNZ_ * NH_ * HD_];     // [tok, h, d] fp32
__device__ float g_k[(size_t)NNZ_ * NKV_ * HD_];
__device__ float g_v[(size_t)NNZ_ * NKV_ * HD_];
__device__ float g_attn[(size_t)NNZ_ * NH_ * HD_];

// bf16 split planes (hi/lo)
__device__ __nv_bfloat16 g_hs_h[(size_t)NNZ_ * HID_];
__device__ __nv_bfloat16 g_hs_l[(size_t)NNZ_ * HID_];
__device__ __nv_bfloat16 g_wq_h[(size_t)(NH_ * HD_) * HID_];
__device__ __nv_bfloat16 g_wq_l[(size_t)(NH_ * HD_) * HID_];
__device__ __nv_bfloat16 g_wk_h[(size_t)(NKV_ * HD_) * HID_];
__device__ __nv_bfloat16 g_wk_l[(size_t)(NKV_ * HD_) * HID_];
__device__ __nv_bfloat16 g_wv_h[(size_t)(NKV_ * HD_) * HID_];
__device__ __nv_bfloat16 g_wv_l[(size_t)(NKV_ * HD_) * HID_];
__device__ __nv_bfloat16 g_wo_h[(size_t)HID_ * (NH_ * HD_)];
__device__ __nv_bfloat16 g_wo_l[(size_t)HID_ * (NH_ * HD_)];
__device__ __nv_bfloat16 g_at_h[(size_t)NNZ_ * (NH_ * HD_)];
__device__ __nv_bfloat16 g_at_l[(size_t)NNZ_ * (NH_ * HD_)];

// ---------------------------------------------------------------------------
// PTX helpers — sm_80-compatible vocabulary ONLY (harness PTX targets
// compute_103 without the 'a' suffix, so tcgen05/TMA are unavailable).
// ---------------------------------------------------------------------------
__device__ __forceinline__ uint32_t s2u(const void* p) {
    uint32_t a;
    asm("{ .reg .u64 t; cvta.to.shared.u64 t, %1; cvt.u32.u64 %0, t; }"
        : "=r"(a) : "l"(p));
    return a;
}

__device__ __forceinline__ void cp16(uint32_t s, const void* g) {
    asm volatile("cp.async.cg.shared.global [%0], [%1], 16;" :: "r"(s), "l"(g));
}
#define CP_COMMIT() asm volatile("cp.async.commit_group;" ::: "memory")
#define CP_WAIT(n)  asm volatile("cp.async.wait_group %0;" :: "n"(n) : "memory")

__device__ __forceinline__ void ldm_x4(uint32_t* r, uint32_t addr) {
    asm volatile("ldmatrix.sync.aligned.m8n8.x4.shared.b16 {%0,%1,%2,%3}, [%4];"
                 : "=r"(r[0]), "=r"(r[1]), "=r"(r[2]), "=r"(r[3]) : "r"(addr));
}

__device__ __forceinline__ void mma16816(float* d, const uint32_t* a,
                                         const uint32_t* b) {
    asm volatile(
        "mma.sync.aligned.m16n8k16.row.col.f32.bf16.bf16.f32 "
        "{%0,%1,%2,%3}, {%4,%5,%6,%7}, {%8,%9}, {%0,%1,%2,%3};"
        : "+f"(d[0]), "+f"(d[1]), "+f"(d[2]), "+f"(d[3])
        : "r"(a[0]), "r"(a[1]), "r"(a[2]), "r"(a[3]), "r"(b[0]), "r"(b[1]));
}

// ---------------------------------------------------------------------------
// Split fp32 -> (bf16 hi, bf16 lo) planes.
// ---------------------------------------------------------------------------
__global__ void split_fp32_bf16(const float* __restrict__ src,
                                __nv_bfloat16* __restrict__ hi,
                                __nv_bfloat16* __restrict__ lo) {
    size_t i = (size_t)blockIdx.x * blockDim.x + threadIdx.x;
    float4 v = ((const float4*)src)[i];
    float x[4] = {v.x, v.y, v.z, v.w};
    union { __nv_bfloat16 b[4]; ushort4 u; } H, L;
#pragma unroll
    for (int j = 0; j < 4; ++j) {
        H.b[j] = __float2bfloat16(x[j]);
        L.b[j] = __float2bfloat16(x[j] - __bfloat162float(H.b[j]));
    }
    ((ushort4*)hi)[i] = H.u;
    ((ushort4*)lo)[i] = L.u;
}

// ---------------------------------------------------------------------------
// bf16-split GEMM via mma.sync: C[M,N] = (Ah+Al)[M,K]*(Bh+Bl)[N,K]^T, minus
// the negligible Al*Bl term. Block tile 128x256, BK=32, 3-stage cp.async,
// 8 warps as 2(M)x4(N), warp tile 64x64 (4 M-frags x 8 N-tiles x 3 products).
// 24 MAC/byte of smem traffic -> tensor-bound (R8's 32x64 tile was at the
// 128B/cyc smem crossbar ceiling).
// smem/stage: Ah[128][32] 8K | Al 8K | Bh[256][32] 16K | Bl 16K = 48KB; x3.
// Swizzle: 16B chunk (row, cg) at row*64 + ((cg ^ ((row>>1)&3))<<4).
// ---------------------------------------------------------------------------
#define A_PLANE   8192
#define B_PLANE   16384
#define STAGE_B   (2 * A_PLANE + 2 * B_PLANE)      // 49152
#define G_SMEM    (3 * STAGE_B)                    // 147456

__global__ __launch_bounds__(256, 1)
void gemm_mma_split(const __nv_bfloat16* __restrict__ Ah,
                    const __nv_bfloat16* __restrict__ Al,
                    const __nv_bfloat16* __restrict__ Bh,
                    const __nv_bfloat16* __restrict__ Bl,
                    float* __restrict__ C, int N, int K) {
    extern __shared__ char smc[];
    const uint32_t sb = s2u(smc);
    const int tid  = threadIdx.x;
    const int wid  = tid >> 5, lane = tid & 31;
    const int wm   = wid >> 2, wn = wid & 3;       // warp grid 2(M) x 4(N)
    const int m0   = blockIdx.y * 128, n0 = blockIdx.x * 256;

    // ---- cp.async geometry: 2 threads/row, two 16B chunks each ----
    const int lrow = tid >> 1;                     // 0..127
    const int cg0  = (tid & 1) * 2;
    const __nv_bfloat16* gAh = Ah + (size_t)(m0 + lrow) * K + cg0 * 8;
    const __nv_bfloat16* gAl = Al + (size_t)(m0 + lrow) * K + cg0 * 8;
    const __nv_bfloat16* gBh = Bh + (size_t)(n0 + lrow) * K + cg0 * 8;
    const __nv_bfloat16* gBl = Bl + (size_t)(n0 + lrow) * K + cg0 * 8;
    const size_t rowskip = (size_t)128 * K;        // B rows 128..255
    const int swl = (lrow >> 1) & 3;
    uint32_t soff[2];
    soff[0] = lrow * 64 + (((cg0 + 0) ^ swl) << 4);
    soff[1] = lrow * 64 + (((cg0 + 1) ^ swl) << 4);
    // row+128 has identical swizzle phase (128 ≡ 0 mod 4 after >>1): +8192

#define LOAD_CHUNK(kt, st) do {                                           \
        uint32_t b_ = sb + (st) * STAGE_B;                                \
        size_t  g_ = (size_t)(kt) * 32;                                   \
        cp16(b_ + soff[0],                      gAh + g_);                \
        cp16(b_ + soff[1],                      gAh + g_ + 8);            \
        cp16(b_ + A_PLANE + soff[0],            gAl + g_);                \
        cp16(b_ + A_PLANE + soff[1],            gAl + g_ + 8);            \
        cp16(b_ + 2 * A_PLANE + soff[0],        gBh + g_);                \
        cp16(b_ + 2 * A_PLANE + soff[1],        gBh + g_ + 8);            \
        cp16(b_ + 2 * A_PLANE + 8192 + soff[0], gBh + g_ + rowskip);      \
        cp16(b_ + 2 * A_PLANE + 8192 + soff[1], gBh + g_ + rowskip + 8);  \
        cp16(b_ + 2 * A_PLANE + B_PLANE + soff[0],        gBl + g_);      \
        cp16(b_ + 2 * A_PLANE + B_PLANE + soff[1],        gBl + g_ + 8);  \
        cp16(b_ + 2 * A_PLANE + B_PLANE + 8192 + soff[0], gBl + g_ + rowskip);     \
        cp16(b_ + 2 * A_PLANE + B_PLANE + 8192 + soff[1], gBl + g_ + rowskip + 8); \
        CP_COMMIT();                                                      \
    } while (0)

    // ---- ldmatrix address offsets (per lane, within a plane) ----
    uint32_t aoff[4][2];                           // A: 4 m-frags x 2 k-halves
#pragma unroll
    for (int t = 0; t < 4; ++t) {
        int row = wm * 64 + t * 16 + (lane & 15);
        int sw  = (row >> 1) & 3;
#pragma unroll
        for (int h = 0; h < 2; ++h) {
            int cg = 2 * h + (lane >> 4);
            aoff[t][h] = row * 64 + ((cg ^ sw) << 4);
        }
    }
    uint32_t boff[4][2];                           // B: 4 n-pairs x 2 k-halves
#pragma unroll
    for (int j = 0; j < 4; ++j) {
        int row = wn * 64 + j * 16 + ((lane >> 4) << 3) + (lane & 7);
        int sw  = (row >> 1) & 3;
#pragma unroll
        for (int h = 0; h < 2; ++h) {
            int cg = 2 * h + ((lane >> 3) & 1);
            boff[j][h] = row * 64 + ((cg ^ sw) << 4);
        }
    }

    float acc[4][8][4];
#pragma unroll
    for (int t = 0; t < 4; ++t)
#pragma unroll
        for (int n = 0; n < 8; ++n)
#pragma unroll
            for (int e = 0; e < 4; ++e) acc[t][n][e] = 0.0f;

    const int nkt = K >> 5;            // K-chunks of 32
    LOAD_CHUNK(0, 0);
    LOAD_CHUNK(1, 1);

    for (int kt = 0; kt < nkt; ++kt) {
        const int s = kt % 3;
        if (kt + 1 < nkt) { CP_WAIT(1); } else { CP_WAIT(0); }
        __syncthreads();               // stage s resident; prev compute done
        if (kt + 2 < nkt) LOAD_CHUNK(kt + 2, (kt + 2) % 3);

        const uint32_t pA_h = sb + s * STAGE_B;
        const uint32_t pA_l = pA_h + A_PLANE;
        const uint32_t pB_h = pA_h + 2 * A_PLANE;
        const uint32_t pB_l = pB_h + B_PLANE;

#pragma unroll
        for (int h = 0; h < 2; ++h) {  // two k16 steps per BK=32
            uint32_t ah[4][4], al[4][4], bh[4][4], bl[4][4];
#pragma unroll
            for (int t = 0; t < 4; ++t) {
                ldm_x4(ah[t], pA_h + aoff[t][h]);
                ldm_x4(al[t], pA_l + aoff[t][h]);
            }
#pragma unroll
            for (int j = 0; j < 4; ++j) {
                ldm_x4(bh[j], pB_h + boff[j][h]);
                ldm_x4(bl[j], pB_l + boff[j][h]);
            }
#pragma unroll
            for (int t = 0; t < 4; ++t)
#pragma unroll
                for (int j = 0; j < 4; ++j) {
                    mma16816(acc[t][2 * j],     ah[t], &bh[j][0]);
                    mma16816(acc[t][2 * j + 1], ah[t], &bh[j][2]);
                    mma16816(acc[t][2 * j],     ah[t], &bl[j][0]);
                    mma16816(acc[t][2 * j + 1], ah[t], &bl[j][2]);
                    mma16816(acc[t][2 * j],     al[t], &bh[j][0]);
                    mma16816(acc[t][2 * j + 1], al[t], &bh[j][2]);
                }
        }
    }

    // ---- epilogue: d-frag lane mapping (row = l>>2 (+8), col = 2*(l&3)) ----
    float* Cw = C + (size_t)(m0 + wm * 64) * N + n0 + wn * 64;
#pragma unroll
    for (int t = 0; t < 4; ++t)
#pragma unroll
        for (int n = 0; n < 8; ++n) {
            int r = t * 16 + (lane >> 2);
            int c = n * 8 + (lane & 3) * 2;
            *(float2*)&Cw[(size_t)r * N + c] =
                make_float2(acc[t][n][0], acc[t][n][1]);
            *(float2*)&Cw[(size_t)(r + 8) * N + c] =
                make_float2(acc[t][n][2], acc[t][n][3]);
        }
#undef LOAD_CHUNK
}

// ---------------------------------------------------------------------------
// Llama-3.1 RoPE in place on Q (32 heads) and K (8 heads). Block=token.
// ---------------------------------------------------------------------------
__global__ void rope_kernel(const int* __restrict__ pos_ids) {
    const int tok = blockIdx.x;
    const int d = threadIdx.x;                 // 0..63
    const float p = (float)pos_ids[tok];

    float fr = (float)pow(500000.0, -(double)d / 64.0);
    const float two_pi = 6.283185307179586f;
    float wav = two_pi / fr;
    float f;
    if (wav < 2048.0f)       f = fr;
    else if (wav > 8192.0f)  f = fr * 0.125f;
    else {
        float smooth = (8192.0f / wav - 1.0f) * (1.0f / 3.0f);
        f = (1.0f - smooth) * fr * 0.125f + smooth * fr;
    }
    float ang = p * f;
    float c = cosf(ang), s = sinf(ang);

    float* qb = g_q + (size_t)tok * (NH_ * HD_);
#pragma unroll 4
    for (int h = 0; h < NH_; ++h) {
        float x1 = qb[h * HD_ + d];
        float x2 = qb[h * HD_ + d + 64];
        qb[h * HD_ + d]      = x1 * c - x2 * s;
        qb[h * HD_ + d + 64] = x2 * c + x1 * s;
    }
    float* kb = g_k + (size_t)tok * (NKV_ * HD_);
#pragma unroll
    for (int h = 0; h < NKV_; ++h) {
        float x1 = kb[h * HD_ + d];
        float x2 = kb[h * HD_ + d + 64];
        kb[h * HD_ + d]      = x1 * c - x2 * s;
        kb[h * HD_ + d + 64] = x2 * c + x1 * s;
    }
}

// ---------------------------------------------------------------------------
// Flash attention (fp32, causal, GQA 4:1) — unchanged (passing since R3).
// ---------------------------------------------------------------------------
#define FA_SMEM_FLOATS (8192 + 8192 + 8192 + 64 * 65)
#define FA_SMEM_BYTES  (FA_SMEM_FLOATS * 4)

__global__ __launch_bounds__(256)
void fa_kernel() {
    extern __shared__ float smf[];
    float* qs = smf;               // [128][64]
    float* ks = smf + 8192;        // [128][64]
    float* vs = smf + 16384;       // [64][128]
    float* ps = smf + 24576;       // [64][65]

    const int qt = blockIdx.x;
    const int h  = blockIdx.y;
    const int b  = blockIdx.z;
    const int hk = h >> 2;
    const int tid = threadIdx.x;
    const int tm = tid >> 4;
    const int tn = tid & 15;
    const int q0 = qt * 64;
    const size_t tok0 = (size_t)b * S_ + q0;
    const float scale = 0.08838834764831845f;

    {
        const float* gq = g_q + tok0 * (NH_ * HD_) + (size_t)h * HD_;
#pragma unroll
        for (int it = 0; it < 8; ++it) {
            int lin = it * 256 + tid;
            int row = lin >> 5;
            int c4  = (lin & 31) * 4;
            float4 v = *(const float4*)(gq + (size_t)row * (NH_ * HD_) + c4);
            qs[(c4 + 0) * 64 + row] = v.x * scale;
            qs[(c4 + 1) * 64 + row] = v.y * scale;
            qs[(c4 + 2) * 64 + row] = v.z * scale;
            qs[(c4 + 3) * 64 + row] = v.w * scale;
        }
    }

    float o[4][8];
#pragma unroll
    for (int i = 0; i < 4; ++i)
#pragma unroll
        for (int j = 0; j < 8; ++j) o[i][j] = 0.0f;
    float mrun[4] = {-1e30f, -1e30f, -1e30f, -1e30f};
    float lrun[4] = {0.0f, 0.0f, 0.0f, 0.0f};

    for (int jt = 0; jt <= qt; ++jt) {
        const float* gk = g_k + ((size_t)b * S_ + jt * 64) * (NKV_ * HD_) + (size_t)hk * HD_;
        const float* gv = g_v + ((size_t)b * S_ + jt * 64) * (NKV_ * HD_) + (size_t)hk * HD_;
#pragma unroll
        for (int it = 0; it < 8; ++it) {
            int lin = it * 256 + tid;
            int row = lin >> 5;
            int c4  = (lin & 31) * 4;
            float4 kv = *(const float4*)(gk + (size_t)row * (NKV_ * HD_) + c4);
            ks[(c4 + 0) * 64 + row] = kv.x;
            ks[(c4 + 1) * 64 + row] = kv.y;
            ks[(c4 + 2) * 64 + row] = kv.z;
            ks[(c4 + 3) * 64 + row] = kv.w;
            float4 vv = *(const float4*)(gv + (size_t)row * (NKV_ * HD_) + c4);
            *(float4*)&vs[row * 128 + c4] = vv;
        }
        __syncthreads();

        float s[4][4];
#pragma unroll
        for (int i = 0; i < 4; ++i)
#pragma unroll
            for (int j = 0; j < 4; ++j) s[i][j] = 0.0f;

#pragma unroll 4
        for (int d = 0; d < 128; ++d) {
            float4 aq = *(const float4*)&qs[d * 64 + tm * 4];
            float4 kq = *(const float4*)&ks[d * 64 + tn * 4];
            float aa[4] = {aq.x, aq.y, aq.z, aq.w};
            float bb[4] = {kq.x, kq.y, kq.z, kq.w};
#pragma unroll
            for (int i = 0; i < 4; ++i)
#pragma unroll
                for (int j = 0; j < 4; ++j)
                    s[i][j] = fmaf(aa[i], bb[j], s[i][j]);
        }

        if (jt == qt) {
#pragma unroll
            for (int i = 0; i < 4; ++i) {
                int ql = tm * 4 + i;
#pragma unroll
                for (int j = 0; j < 4; ++j) {
                    int kl = tn * 4 + j;
                    if (kl > ql) s[i][j] = -1e30f;
                }
            }
        }

        float corr[4];
#pragma unroll
        for (int i = 0; i < 4; ++i) {
            float t = fmaxf(fmaxf(s[i][0], s[i][1]), fmaxf(s[i][2], s[i][3]));
            t = fmaxf(t, __shfl_xor_sync(0xffffffffu, t, 8));
            t = fmaxf(t, __shfl_xor_sync(0xffffffffu, t, 4));
            t = fmaxf(t, __shfl_xor_sync(0xffffffffu, t, 2));
            t = fmaxf(t, __shfl_xor_sync(0xffffffffu, t, 1));
            float mnew = fmaxf(mrun[i], t);
            corr[i] = __expf(mrun[i] - mnew);
            mrun[i] = mnew;
        }
#pragma unroll
        for (int i = 0; i < 4; ++i) {
            float rs = 0.0f;
#pragma unroll
            for (int j = 0; j < 4; ++j) {
                float pp = __expf(s[i][j] - mrun[i]);
                ps[(tn * 4 + j) * 65 + tm * 4 + i] = pp;
                rs += pp;
            }
            rs += __shfl_xor_sync(0xffffffffu, rs, 8);
            rs += __shfl_xor_sync(0xffffffffu, rs, 4);
            rs += __shfl_xor_sync(0xffffffffu, rs, 2);
            rs += __shfl_xor_sync(0xffffffffu, rs, 1);
            lrun[i] = lrun[i] * corr[i] + rs;
#pragma unroll
            for (int j = 0; j < 8; ++j) o[i][j] *= corr[i];
        }
        __syncthreads();

#pragma unroll 2
        for (int c = 0; c < 64; ++c) {
            float p0 = ps[c * 65 + tm * 4 + 0];
            float p1 = ps[c * 65 + tm * 4 + 1];
            float p2 = ps[c * 65 + tm * 4 + 2];
            float p3 = ps[c * 65 + tm * 4 + 3];
            float4 v0 = *(const float4*)&vs[c * 128 + tn * 8];
            float4 v1 = *(const float4*)&vs[c * 128 + tn * 8 + 4];
            float vv[8] = {v0.x, v0.y, v0.z, v0.w, v1.x, v1.y, v1.z, v1.w};
#pragma unroll
            for (int j = 0; j < 8; ++j) {
                o[0][j] = fmaf(p0, vv[j], o[0][j]);
                o[1][j] = fmaf(p1, vv[j], o[1][j]);
                o[2][j] = fmaf(p2, vv[j], o[2][j]);
                o[3][j] = fmaf(p3, vv[j], o[3][j]);
            }
        }
        __syncthreads();
    }

#pragma unroll
    for (int i = 0; i < 4; ++i) {
        float inv = 1.0f / lrun[i];
        float* dst = g_attn + (tok0 + tm * 4 + i) * (size_t)(NH_ * HD_)
                     + (size_t)h * HD_ + tn * 8;
        *(float4*)(dst)     = make_float4(o[i][0] * inv, o[i][1] * inv,
                                          o[i][2] * inv, o[i][3] * inv);
        *(float4*)(dst + 4) = make_float4(o[i][4] * inv, o[i][5] * inv,
                                          o[i][6] * inv, o[i][7] * inv);
    }
}

// ---------------------------------------------------------------------------
// Launch: split -> mma GEMMs (QKV) -> RoPE -> FA -> split -> mma GEMM (O).
// kv_cache append is skipped (identity round-trip; cache not an output).
// ---------------------------------------------------------------------------
extern "C" void kernel_launch(void* const* d_in, const int* in_sizes, int n_in,
                              void* d_out, int out_size) {
    const float* hs = (const float*)d_in[0];
    const float* wq = (const float*)d_in[1];
    const float* wk = (const float*)d_in[2];
    const float* wv = (const float*)d_in[3];
    const float* wo = (const float*)d_in[4];
    const int* pos  = (const int*)d_in[6];
    float* out = (float*)d_out;

    float *pq, *pk, *pv, *pa;
    cudaGetSymbolAddress((void**)&pq, g_q);
    cudaGetSymbolAddress((void**)&pk, g_k);
    cudaGetSymbolAddress((void**)&pv, g_v);
    cudaGetSymbolAddress((void**)&pa, g_attn);

    __nv_bfloat16 *hsh, *hsl, *wqh, *wql, *wkh, *wkl, *wvh, *wvl, *woh, *wol, *ath, *atl;
    cudaGetSymbolAddress((void**)&hsh, g_hs_h); cudaGetSymbolAddress((void**)&hsl, g_hs_l);
    cudaGetSymbolAddress((void**)&wqh, g_wq_h); cudaGetSymbolAddress((void**)&wql, g_wq_l);
    cudaGetSymbolAddress((void**)&wkh, g_wk_h); cudaGetSymbolAddress((void**)&wkl, g_wk_l);
    cudaGetSymbolAddress((void**)&wvh, g_wv_h); cudaGetSymbolAddress((void**)&wvl, g_wv_l);
    cudaGetSymbolAddress((void**)&woh, g_wo_h); cudaGetSymbolAddress((void**)&wol, g_wo_l);
    cudaGetSymbolAddress((void**)&ath, g_at_h); cudaGetSymbolAddress((void**)&atl, g_at_l);

    cudaFuncSetAttribute(fa_kernel, cudaFuncAttributeMaxDynamicSharedMemorySize,
                         FA_SMEM_BYTES);
    cudaFuncSetAttribute(gemm_mma_split, cudaFuncAttributeMaxDynamicSharedMemorySize,
                         G_SMEM);

    const int BIG4 = (NNZ_ * HID_) / 1024;          // 256 thr x 4 elems/thread
    const int SML4 = (NKV_ * HD_ * HID_) / 1024;

    // split inputs/weights to bf16 hi/lo planes
    split_fp32_bf16<<<BIG4, 256>>>(hs, hsh, hsl);
    split_fp32_bf16<<<BIG4, 256>>>(wq, wqh, wql);
    split_fp32_bf16<<<SML4, 256>>>(wk, wkh, wkl);
    split_fp32_bf16<<<SML4, 256>>>(wv, wvh, wvl);
    split_fp32_bf16<<<BIG4, 256>>>(wo, woh, wol);

    // QKV projections (tensor cores via mma.sync), N-tile = 256
    gemm_mma_split<<<dim3((NH_ * HD_) / 256, NNZ_ / 128), 256, G_SMEM>>>(
        hsh, hsl, wqh, wql, pq, NH_ * HD_, HID_);
    gemm_mma_split<<<dim3((NKV_ * HD_) / 256, NNZ_ / 128), 256, G_SMEM>>>(
        hsh, hsl, wkh, wkl, pk, NKV_ * HD_, HID_);
    gemm_mma_split<<<dim3((NKV_ * HD_) / 256, NNZ_ / 128), 256, G_SMEM>>>(
        hsh, hsl, wvh, wvl, pv, NKV_ * HD_, HID_);

    // RoPE (in place, fp32)
    rope_kernel<<<NNZ_, 64>>>(pos);

    // Causal GQA attention (fp32)
    fa_kernel<<<dim3(S_ / 64, NH_, B_), 256, FA_SMEM_BYTES>>>();

    // split attention output, then O projection
    split_fp32_bf16<<<BIG4, 256>>>(pa, ath, atl);
    gemm_mma_split<<<dim3(HID_ / 256, NNZ_ / 128), 256, G_SMEM>>>(
        ath, atl, woh, wol, out, HID_, NH_ * HD_);
}